// round 7
// baseline (speedup 1.0000x reference)
#include <cuda_runtime.h>
#include <cuda.h>
#include <cuda_bf16.h>
#include <cstdint>

// FlowUpSampler convex upsampling — TMA-fed smem pipeline.
// flow: [N=8, 2, H=64, W=128] f32
// mask: [N, 576, H, W] f32 viewed as [n][k(9)][a(8)][b(8)][h][w]
// out:  [N, 2, 512, 1024] f32, out[n][c][8h+a][8w+b]
//
// 5D tensormap over mask: dims (w0=64, w1=2, h=64, ab=64, nk=72); one
// cp.async.bulk.tensor.5d per (n,a,h) delivers the full 36KB [k=9][b=8][w=128]
// slice to smem. Block = (n, a, h-pair): 2 stages, double-buffered tiles,
// mbarrier completion. 256 threads = (b, lane4) compute softmax+combine from
// smem; coalesced float4 stores via an 8KB smem transpose.

#define H_ 64
#define W_ 128

#define TILE_BYTES 36864                    // 9*8*128*4
#define OFF_MBAR   0
#define OFF_TILE0  1024
#define OFF_TILE1  (1024 + TILE_BYTES)
#define OFF_SF     (1024 + 2 * TILE_BYTES)  // float sf[2][4][136]
#define SF_BYTES   (2 * 4 * 136 * 4)
#define OFF_SO     (OFF_SF + SF_BYTES)      // float so[2][8][128]
#define SO_BYTES   (2 * 8 * 128 * 4)
#define SMEM_TOTAL (OFF_SO + SO_BYTES)

#define MBARRIER_INIT(addr, cnt) \
    asm volatile("mbarrier.init.shared.b64 [%0], %1;" :: "r"(addr), "r"(cnt) : "memory")
#define MBARRIER_EXPECT_TX(addr, bytes) \
    asm volatile("mbarrier.arrive.expect_tx.shared.b64 _, [%0], %1;" \
                 :: "r"(addr), "r"(bytes) : "memory")
#define MBARRIER_WAIT_PARITY(addr, parity) do {                                   \
    asm volatile(                                                                 \
        "{\n\t.reg .pred P1;\n\t"                                                 \
        "WAIT_LOOP_%=:\n\t"                                                       \
        "mbarrier.try_wait.parity.acquire.cta.shared::cta.b64 P1, [%0], %1, 0x989680;\n\t" \
        "@P1 bra.uni WAIT_DONE_%=;\n\t"                                           \
        "bra.uni WAIT_LOOP_%=;\n\t"                                               \
        "WAIT_DONE_%=:\n\t}"                                                      \
        :: "r"(addr), "r"(parity) : "memory");                                    \
} while (0)

#define TMA_LOAD_5D(dst, map, c0, c1, c2, c3, c4, mbar)                           \
    asm volatile(                                                                 \
        "cp.async.bulk.tensor.5d.shared::cta.global.tile.mbarrier::complete_tx::bytes " \
        "[%0], [%1, {%2, %3, %4, %5, %6}], [%7];"                                 \
        :: "r"(dst), "l"(map), "r"(c0), "r"(c1), "r"(c2), "r"(c3), "r"(c4),       \
           "r"(mbar) : "memory")

__global__ __launch_bounds__(256, 2)
void flow_up_tma(const __grid_constant__ CUtensorMap tmap,
                 const float* __restrict__ flow,
                 float* __restrict__ out)
{
    extern __shared__ char smem[];
    const int tid = threadIdx.x;
    const int b   = tid >> 5;          // 0..7
    const int l   = tid & 31;          // lane: w = 4l..4l+3
    const int bx  = blockIdx.x;
    const int hc = bx & 31;            // 32 h-pairs
    const int a  = (bx >> 5) & 7;
    const int n  = bx >> 8;
    const int h0 = hc * 2;

    float* sf = (float*)(smem + OFF_SF);   // [2][4][136]: rows h0-1..h0+2
    float* so = (float*)(smem + OFF_SO);   // [2][8][128]
    const uint32_t mbar0 = (uint32_t)__cvta_generic_to_shared(smem + OFF_MBAR);
    const uint32_t mbar1 = mbar0 + 8;
    const uint32_t t0 = (uint32_t)__cvta_generic_to_shared(smem + OFF_TILE0);
    const uint32_t t1 = (uint32_t)__cvta_generic_to_shared(smem + OFF_TILE1);

    if (tid == 0) {
        MBARRIER_INIT(mbar0, 1);
        MBARRIER_INIT(mbar1, 1);
        asm volatile("fence.proxy.async.shared::cta;" ::: "memory");
    }
    __syncthreads();

    if (tid == 0) {
        MBARRIER_EXPECT_TX(mbar0, TILE_BYTES);
        TMA_LOAD_5D(t0, &tmap, 0, 0, h0, a * 8, n * 9, mbar0);
    }

    // flow slab: rows h0-1..h0+2 (4), halo'd cols (130 used, 136 stride for f4 alignment)
    for (int i2 = tid; i2 < 2 * 4 * 130; i2 += 256) {
        int c  = i2 / (4 * 130);
        int r  = (i2 / 130) % 4;
        int x  = i2 % 130;
        int hh = h0 - 1 + r;
        int ww = x - 1;
        float v = 0.0f;
        if ((unsigned)hh < H_ && (unsigned)ww < W_)
            v = 8.0f * flow[(((size_t)n * 2 + c) * H_ + hh) * W_ + ww];
        sf[(c * 4 + r) * 136 + x] = v;
    }
    __syncthreads();

    float4* out4 = (float4*)out;
    const int w_ = tid >> 1;            // store-phase gather coords
    const int b0 = (tid & 1) * 4;

#pragma unroll
    for (int i = 0; i < 2; i++) {
        if (i == 0 && tid == 0) {       // prefetch stage 1
            MBARRIER_EXPECT_TX(mbar1, TILE_BYTES);
            TMA_LOAD_5D(t1, &tmap, 0, 0, h0 + 1, a * 8, n * 9, mbar1);
        }

        // patch windows for h = h0+i: slab rows i..i+2
        float P0[3][6], P1[3][6];
#pragma unroll
        for (int di = 0; di < 3; di++) {
            const float* r0 = &sf[(0 * 4 + i + di) * 136 + 4 * l];
            float4 v = *(const float4*)r0;
            P0[di][0] = v.x; P0[di][1] = v.y; P0[di][2] = v.z; P0[di][3] = v.w;
            P0[di][4] = r0[4]; P0[di][5] = r0[5];
            const float* r1 = &sf[(1 * 4 + i + di) * 136 + 4 * l];
            float4 u = *(const float4*)r1;
            P1[di][0] = u.x; P1[di][1] = u.y; P1[di][2] = u.z; P1[di][3] = u.w;
            P1[di][4] = r1[4]; P1[di][5] = r1[5];
        }

        MBARRIER_WAIT_PARITY(i ? mbar1 : mbar0, 0);

        const float* tile = (const float*)(smem + (i ? OFF_TILE1 : OFF_TILE0));
        float4 s  = make_float4(0.f, 0.f, 0.f, 0.f);
        float4 A0 = s, A1 = s;
#pragma unroll
        for (int k = 0; k < 9; k++) {
            const int di = k / 3, dj = k % 3;
            float4 mv = *(const float4*)(tile + ((k * 8 + b) * 128 + 4 * l));
            float4 e;
            e.x = __expf(mv.x); e.y = __expf(mv.y);
            e.z = __expf(mv.z); e.w = __expf(mv.w);
            s.x += e.x; s.y += e.y; s.z += e.z; s.w += e.w;
            A0.x = fmaf(e.x, P0[di][dj + 0], A0.x);
            A0.y = fmaf(e.y, P0[di][dj + 1], A0.y);
            A0.z = fmaf(e.z, P0[di][dj + 2], A0.z);
            A0.w = fmaf(e.w, P0[di][dj + 3], A0.w);
            A1.x = fmaf(e.x, P1[di][dj + 0], A1.x);
            A1.y = fmaf(e.y, P1[di][dj + 1], A1.y);
            A1.z = fmaf(e.z, P1[di][dj + 2], A1.z);
            A1.w = fmaf(e.w, P1[di][dj + 3], A1.w);
        }
        float4 r;
        r.x = __fdividef(1.f, s.x); r.y = __fdividef(1.f, s.y);
        r.z = __fdividef(1.f, s.z); r.w = __fdividef(1.f, s.w);
        *(float4*)&so[(0 * 8 + b) * 128 + 4 * l] =
            make_float4(A0.x * r.x, A0.y * r.y, A0.z * r.z, A0.w * r.w);
        *(float4*)&so[(1 * 8 + b) * 128 + 4 * l] =
            make_float4(A1.x * r.x, A1.y * r.y, A1.z * r.z, A1.w * r.w);
        __syncthreads();

        // coalesced store: out[n][c][8(h0+i)+a][o], o=8w+b -> so[c][o&7][o>>3]
#pragma unroll
        for (int c = 0; c < 2; c++) {
            const size_t base = ((size_t)(n * 2 + c) * 512 + (size_t)8 * (h0 + i) + a) * 256;
            float4 v = make_float4(so[(c * 8 + b0 + 0) * 128 + w_],
                                   so[(c * 8 + b0 + 1) * 128 + w_],
                                   so[(c * 8 + b0 + 2) * 128 + w_],
                                   so[(c * 8 + b0 + 3) * 128 + w_]);
            __stcs(&out4[base + tid], v);
        }
        __syncthreads();   // so + tile buffer reusable
    }
}

extern "C" void kernel_launch(void* const* d_in, const int* in_sizes, int n_in,
                              void* d_out, int out_size)
{
    const float* flow = (const float*)d_in[0];
    const float* mask = (const float*)d_in[1];
    float* out = (float*)d_out;
    (void)in_sizes; (void)n_in; (void)out_size;

    // Build the 5D tensormap (pure host; deterministic per call).
    typedef CUresult (*EncFn)(CUtensorMap*, CUtensorMapDataType, cuuint32_t, void*,
                              const cuuint64_t*, const cuuint64_t*, const cuuint32_t*,
                              const cuuint32_t*, CUtensorMapInterleave, CUtensorMapSwizzle,
                              CUtensorMapL2promotion, CUtensorMapFloatOOBfill);
    void* fp = nullptr;
    cudaDriverEntryPointQueryResult qres;
    cudaGetDriverEntryPoint("cuTensorMapEncodeTiled", &fp, cudaEnableDefault, &qres);
    EncFn enc = (EncFn)fp;

    CUtensorMap tmap;
    // mask element (n,k,a,b,h,w), w = 2*w1*? -> dims innermost-first:
    //   d0 w0:64 (4B elems), d1 w1:2 (256B), d2 h:64 (512B), d3 ab:64 (32KB),
    //   d4 nk:72 (2MB)  [n stride = 9 * k stride -> fused axis]
    cuuint64_t dims[5]    = {64, 2, 64, 64, 72};
    cuuint64_t strides[4] = {256, 512, 32768, 2097152};   // bytes, dims 1..4
    cuuint32_t box[5]     = {64, 2, 1, 8, 9};             // 36KB: [k9][b8][w128]
    cuuint32_t estr[5]    = {1, 1, 1, 1, 1};
    enc(&tmap, CU_TENSOR_MAP_DATA_TYPE_FLOAT32, 5, (void*)mask,
        dims, strides, box, estr,
        CU_TENSOR_MAP_INTERLEAVE_NONE, CU_TENSOR_MAP_SWIZZLE_NONE,
        CU_TENSOR_MAP_L2_PROMOTION_L2_128B, CU_TENSOR_MAP_FLOAT_OOB_FILL_NONE);

    cudaFuncSetAttribute(flow_up_tma, cudaFuncAttributeMaxDynamicSharedMemorySize,
                         SMEM_TOTAL);

    // grid = 8n * 8a * 32 h-pairs = 2048 blocks, 256 threads, ~87KB smem
    flow_up_tma<<<2048, 256, SMEM_TOTAL>>>(tmap, flow, out);
}

// round 8
// speedup vs baseline: 1.1079x; 1.1079x over previous
#include <cuda_runtime.h>
#include <cuda_bf16.h>

// FlowUpSampler convex upsampling — h-pair blocks, 18-deep load batches
// (1KB contiguous per (k,b) stream), smem-staged outputs for max occupancy.
// flow: [N=8, 2, H=64, W=128] f32
// mask: [N, 576, H, W] f32 viewed as [n][k(9)][a(8)][b(8)][h][w]
// out:  [N, 2, 512, 1024] f32, out[n][c][8h+a][8w+b]
//
// Block = (n, a, h0 in steps of 2); 128 threads = w. Per b: 18 coalesced
// scalar mask loads (9 k-streams x 2 adjacent h rows -> 1KB contiguous per
// stream), two softmax/combine chains (h0, h0+1), results staged to smem;
// one coalesced float4 store phase at the end.

#define H_ 64
#define W_ 128

__global__ __launch_bounds__(128, 8)
void flow_up_kernel(const float* __restrict__ flow,
                    const float* __restrict__ mask,
                    float* __restrict__ out)
{
    const int w   = threadIdx.x;
    const int bid = blockIdx.x;
    const int hp = bid & 31;             // h-pair index
    const int a  = (bid >> 5) & 7;
    const int n  = bid >> 8;
    const int h0 = hp * 2;

    __shared__ float sf[2][4][132];      // 8*flow rows h0-1..h0+2, halo'd
    __shared__ float so[2][2][8][W_];    // staged outputs [c][hh][b][w]

    for (int i = threadIdx.x; i < 2 * 4 * 130; i += 128) {
        int c  = i / (4 * 130);
        int r  = (i / 130) % 4;
        int x  = i % 130;
        int hh = h0 - 1 + r;
        int ww = x - 1;
        float v = 0.0f;
        if ((unsigned)hh < H_ && (unsigned)ww < W_)
            v = 8.0f * flow[(((size_t)n * 2 + c) * H_ + hh) * W_ + ww];
        sf[c][r][x] = v;
    }
    __syncthreads();

    // patch windows: P[c][r][j] = sf[c][r][w+j], rows 0..3 (h0 uses 0-2, h0+1 uses 1-3)
    float P0[4][3], P1[4][3];
#pragma unroll
    for (int r = 0; r < 4; r++) {
#pragma unroll
        for (int j = 0; j < 3; j++) {
            P0[r][j] = sf[0][r][w + j];
            P1[r][j] = sf[1][r][w + j];
        }
    }

    const size_t HW = (size_t)H_ * W_;   // 8192
    const size_t KS = 64 * HW;           // k stride
    const float* mp = mask + ((size_t)n * 576 + (size_t)a * 8) * HW
                           + (size_t)h0 * W_ + w;

#pragma unroll
    for (int b = 0; b < 8; b++) {
        const float* mb = mp + (size_t)b * HW;
        // 18 front-batched loads: 9 k-streams x 2 adjacent h rows (1KB/stream)
        float m0[9], m1[9];
#pragma unroll
        for (int k = 0; k < 9; k++) {
            m0[k] = __ldcs(mb + (size_t)k * KS);
            m1[k] = __ldcs(mb + (size_t)k * KS + W_);
        }

        // h = h0 (patch rows 0..2)
        {
            float s = 0.f, a0 = 0.f, a1 = 0.f;
#pragma unroll
            for (int k = 0; k < 9; k++) {
                const int di = k / 3, dj = k % 3;
                float e = __expf(m0[k]);
                s += e;
                a0 = fmaf(e, P0[di][dj], a0);
                a1 = fmaf(e, P1[di][dj], a1);
            }
            float r = __fdividef(1.0f, s);
            so[0][0][b][w] = a0 * r;
            so[1][0][b][w] = a1 * r;
        }
        // h = h0+1 (patch rows 1..3)
        {
            float s = 0.f, a0 = 0.f, a1 = 0.f;
#pragma unroll
            for (int k = 0; k < 9; k++) {
                const int di = k / 3, dj = k % 3;
                float e = __expf(m1[k]);
                s += e;
                a0 = fmaf(e, P0[di + 1][dj], a0);
                a1 = fmaf(e, P1[di + 1][dj], a1);
            }
            float r = __fdividef(1.0f, s);
            so[0][1][b][w] = a0 * r;
            so[1][1][b][w] = a1 * r;
        }
    }
    __syncthreads();

    // coalesced store phase: out[n][c][8(h0+hh)+a][o], o = 8w+b,
    // value = so[c][hh][o&7][o>>3]; thread stores one float4 per (c,hh).
    float4* out4 = reinterpret_cast<float4*>(out);
    const int w_ = threadIdx.x >> 1;           // (4*tid)>>3  (tid<128 -> w_<64)
    const int b0 = (threadIdx.x & 1) * 4;      // (4*tid)&7
#pragma unroll
    for (int c = 0; c < 2; c++) {
#pragma unroll
        for (int hh = 0; hh < 2; hh++) {
            const size_t row  = (size_t)(n * 2 + c) * 512 + (size_t)8 * (h0 + hh) + a;
            const size_t base = row * 256;     // float4 per 1024-row
            // thread covers float4 indices tid and tid+128 of this row
#pragma unroll
            for (int half = 0; half < 2; half++) {
                const int idx = threadIdx.x + half * 128;
                const int ww  = (idx >> 1);
                const int bb  = (idx & 1) * 4;
                float4 v = make_float4(so[c][hh][bb + 0][ww], so[c][hh][bb + 1][ww],
                                       so[c][hh][bb + 2][ww], so[c][hh][bb + 3][ww]);
                __stcs(&out4[base + idx], v);
            }
        }
    }
    (void)w_; (void)b0;
}

extern "C" void kernel_launch(void* const* d_in, const int* in_sizes, int n_in,
                              void* d_out, int out_size)
{
    const float* flow = (const float*)d_in[0];
    const float* mask = (const float*)d_in[1];
    float* out = (float*)d_out;
    (void)in_sizes; (void)n_in; (void)out_size;

    // grid = 8n * 8a * 32 h-pairs = 2048 blocks, 128 threads
    flow_up_kernel<<<2048, 128>>>(flow, mask, out);
}